// round 15
// baseline (speedup 1.0000x reference)
#include <cuda_runtime.h>
#include <cuda_fp16.h>
#include <cstdint>

#define B 16
#define NN 1024
#define NF 16
#define NHID 32
#define HEADS 4
#define NP 12
#define LOG2E 1.4426950408889634f
#define ONES16 0x3C003C00u

__device__ float    g_Wh[B*HEADS*NN*NHID];
__device__ float    g_fsrc[B*HEADS*NN];
__device__ float    g_fdst[B*HEADS*NN];
__device__ unsigned g_mask[NN*NN/32];
__device__ float    g_Wh2p[HEADS*B*NN*NP];   // per-head partial projections

__device__ __forceinline__ float ex2f(float x) {
    float y; asm("ex2.approx.f32 %0, %1;" : "=f"(y) : "f"(x)); return y;
}
__device__ __forceinline__ float eluf(float v) { return v > 0.f ? v : (ex2f(v*LOG2E) - 1.f); }

__device__ __forceinline__ unsigned long long ffma2(unsigned long long a, unsigned long long b,
                                                    unsigned long long c) {
    unsigned long long d;
    asm("fma.rn.f32x2 %0, %1, %2, %3;" : "=l"(d) : "l"(a), "l"(b), "l"(c));
    return d;
}
__device__ __forceinline__ unsigned long long addf2(unsigned long long a, unsigned long long b) {
    unsigned long long d;
    asm("add.rn.f32x2 %0, %1, %2;" : "=l"(d) : "l"(a), "l"(b));
    return d;
}
__device__ __forceinline__ unsigned long long pack2(float x) {
    unsigned long long d;
    asm("mov.b64 %0, {%1, %2};" : "=l"(d) : "f"(x), "f"(x));
    return d;
}
__device__ __forceinline__ float2 unpk2(unsigned long long v) {
    float2 f;
    asm("mov.b64 {%0, %1}, %2;" : "=f"(f.x), "=f"(f.y) : "l"(v));
    return f;
}
__device__ __forceinline__ uint32_t pk16(float a, float b) {
    uint32_t h;
    asm("cvt.rn.f16x2.f32 %0, %1, %2;" : "=r"(h) : "f"(b), "f"(a));
    return h;
}
__device__ __forceinline__ uint32_t hadd2u(uint32_t a, uint32_t b) {
    uint32_t d; asm("add.rn.f16x2 %0, %1, %2;" : "=r"(d) : "r"(a), "r"(b)); return d;
}
__device__ __forceinline__ uint32_t hmul2u(uint32_t a, uint32_t b) {
    uint32_t d; asm("mul.rn.f16x2 %0, %1, %2;" : "=r"(d) : "r"(a), "r"(b)); return d;
}
__device__ __forceinline__ uint32_t hmax2u(uint32_t a, uint32_t b) {
    uint32_t d; asm("max.f16x2 %0, %1, %2;" : "=r"(d) : "r"(a), "r"(b)); return d;
}
__device__ __forceinline__ uint32_t ex2h2(uint32_t a) {
    uint32_t d; asm("ex2.approx.f16x2 %0, %1;" : "=r"(d) : "r"(a)); return d;
}
// raw PTX prmt: generic mode honors per-nibble msb sign-replicate (__byte_perm does NOT)
__device__ __forceinline__ uint32_t prmt_sr(uint32_t a, uint32_t b, uint32_t sel) {
    uint32_t d; asm("prmt.b32 %0, %1, %2, %3;" : "=r"(d) : "r"(a), "r"(b), "r"(sel)); return d;
}
__device__ __forceinline__ void mma16h(float* d, const uint32_t* a, uint32_t b0, uint32_t b1) {
    asm("mma.sync.aligned.m16n8k16.row.col.f32.f16.f16.f32 "
        "{%0,%1,%2,%3},{%4,%5,%6,%7},{%8,%9},{%0,%1,%2,%3};"
        : "+f"(d[0]), "+f"(d[1]), "+f"(d[2]), "+f"(d[3])
        : "r"(a[0]), "r"(a[1]), "r"(a[2]), "r"(a[3]), "r"(b0), "r"(b1));
}

// ---------------- K0: adjacency -> bitmask ----------------
__global__ void k_mask(const int* __restrict__ adj) {
    int i = blockIdx.x, j = threadIdx.x;
    unsigned bal = __ballot_sync(0xffffffffu, adj[i*NN + j] > 0);
    if ((j & 31) == 0) g_mask[i*32 + (j >> 5)] = bal;
}

// ---------------- K1: Wh = x@W (f32x2), f_src/f_dst ----------------
__global__ void k_wh(const float* __restrict__ x, const float* __restrict__ W,
                     const float* __restrict__ a_src, const float* __restrict__ a_dst) {
    __shared__ float Ws[NF*NHID], as_s[NHID], ad_s[NHID];
    int bh = blockIdx.x, b = bh >> 2, h = bh & 3, tid = threadIdx.x;
    for (int i = tid; i < NF*NHID; i += 256) Ws[i] = W[h*NF*NHID + i];
    if (tid < NHID) { as_s[tid] = a_src[h*NHID + tid]; ad_s[tid] = a_dst[h*NHID + tid]; }
    __syncthreads();
    int n = blockIdx.y*256 + tid;
    const float4* xp = (const float4*)(x + ((size_t)b*NN + n)*NF);
    float xf[NF];
#pragma unroll
    for (int i = 0; i < NF/4; i++) {
        float4 v = __ldg(xp + i);
        xf[4*i] = v.x; xf[4*i+1] = v.y; xf[4*i+2] = v.z; xf[4*i+3] = v.w;
    }
    unsigned long long wh2[NHID/2];
#pragma unroll
    for (int k2 = 0; k2 < NHID/2; k2++) wh2[k2] = 0ull;
#pragma unroll
    for (int f = 0; f < NF; f++) {
        unsigned long long xv2 = pack2(xf[f]);
        const unsigned long long* wr = (const unsigned long long*)(Ws + f*NHID);
#pragma unroll
        for (int k2 = 0; k2 < NHID/2; k2++) wh2[k2] = ffma2(xv2, wr[k2], wh2[k2]);
    }
    unsigned long long fs2 = 0ull, fd2 = 0ull;
    const unsigned long long* as2 = (const unsigned long long*)as_s;
    const unsigned long long* ad2 = (const unsigned long long*)ad_s;
#pragma unroll
    for (int k2 = 0; k2 < NHID/2; k2++) {
        fs2 = ffma2(wh2[k2], as2[k2], fs2);
        fd2 = ffma2(wh2[k2], ad2[k2], fd2);
    }
    float2 fsp = unpk2(fs2), fdp = unpk2(fd2);
    unsigned long long* op = (unsigned long long*)(g_Wh + ((size_t)bh*NN + n)*NHID);
#pragma unroll
    for (int k2 = 0; k2 < NHID/2; k2++) op[k2] = wh2[k2];
    g_fsrc[bh*NN + n] = fsp.x + fsp.y;
    g_fdst[bh*NN + n] = fdp.x + fdp.y;
}

// ---------------- K2: fused GAT layer 1 + h@W_out partial; 256 thr, 2 CTA/SM ----------------
__global__ void __launch_bounds__(256, 2) k_attn1_f(const float* __restrict__ W_out) {
    extern __shared__ float sm[];
    uint32_t* WhHi = (uint32_t*)sm;              // [32][512] f16x2 (j even/odd pairs)
    uint32_t* fd_h = WhHi + 32*512;              // [512] half2 of fd*LOG2E pairs
    float* Wo = (float*)(fd_h + 512);            // [32][12] W_out slice for this head

    int tid = threadIdx.x, warp = tid >> 5, lane = tid & 31;
    int r = lane & 3, q = lane >> 2;
    int bh = blockIdx.x >> 2, quarter = blockIdx.x & 3;
    int b = bh >> 2, h = bh & 3, row0 = quarter*256;

    const float* Whg = g_Wh + (size_t)bh*NN*NHID;
    for (int idx = tid; idx < NN*NHID/2; idx += 256) {
        int jp = idx >> 5, k = idx & 31;
        float w0 = Whg[(2*jp)*NHID + k];
        float w1 = Whg[(2*jp+1)*NHID + k];
        int jsw = jp ^ ((k & 7) << 2);
        WhHi[k*512 + jsw] = pk16(w0, w1);
    }
    {
        const float* fdg = g_fdst + bh*NN;
        for (int jp = tid; jp < NN/2; jp += 256)
            fd_h[jp] = pk16(fdg[2*jp]*LOG2E, fdg[2*jp+1]*LOG2E);
    }
    for (int i = tid; i < NHID*NP; i += 256) Wo[i] = W_out[h*NHID*NP + i];
    __syncthreads();

    const uint4* mp4[4];
    uint32_t fs2h[4];
#pragma unroll
    for (int t = 0; t < 4; t++) {
        int row = row0 + warp*32 + q + 8*t;
        mp4[t] = (const uint4*)(g_mask + (size_t)row*32);
        float fv = g_fsrc[bh*NN + row] * LOG2E;
        fs2h[t] = pk16(fv, fv);
    }
    const uint32_t C02H = 0x32663266u;

    float acc[2][4][4];
    float accz[2][4];
#pragma unroll
    for (int f = 0; f < 2; f++) {
#pragma unroll
        for (int nt = 0; nt < 4; nt++)
#pragma unroll
            for (int i = 0; i < 4; i++) acc[f][nt][i] = 0.f;
#pragma unroll
        for (int i = 0; i < 4; i++) accz[f][i] = 0.f;
    }

#pragma unroll 1
    for (int gg = 0; gg < 8; gg++) {
        uint4 m4[4];
#pragma unroll
        for (int t = 0; t < 4; t++) m4[t] = __ldg(mp4[t] + gg);
#pragma unroll
        for (int sub = 0; sub < 4; sub++) {
            unsigned mw[4];
#pragma unroll
            for (int t = 0; t < 4; t++)
                mw[t] = (sub == 0) ? m4[t].x : (sub == 1) ? m4[t].y : (sub == 2) ? m4[t].z : m4[t].w;
            int g = gg*4 + sub;
            uint32_t us[4], vs[4];
#pragma unroll
            for (int t = 0; t < 4; t++) {
                us[t] = mw[t] << (7 - 2*r);
                vs[t] = mw[t] << (6 - 2*r);
            }
#pragma unroll
            for (int ck = 0; ck < 2; ck++) {
                int jp0 = g*16 + ck*8;
                uint32_t fdA = fd_h[jp0 + r];
                uint32_t fdB = fd_h[jp0 + 4 + r];
                uint32_t selA = ck ? 0xEEAAu : 0xCC88u;
                uint32_t selB = ck ? 0xFFBBu : 0xDD99u;
                uint32_t Ah[2][4];
#pragma unroll
                for (int f = 0; f < 2; f++) {
#pragma unroll
                    for (int hh = 0; hh < 2; hh++) {
                        int t = 2*f + hh;
                        uint32_t amaskA = prmt_sr(us[t], vs[t], selA);
                        uint32_t amaskB = prmt_sr(us[t], vs[t], selB);
                        uint32_t eA = hadd2u(fs2h[t], fdA);
                        uint32_t eB = hadd2u(fs2h[t], fdB);
                        eA = hmax2u(eA, hmul2u(eA, C02H));
                        eB = hmax2u(eB, hmul2u(eB, C02H));
                        Ah[f][hh]     = ex2h2(eA) & amaskA;
                        Ah[f][2 + hh] = ex2h2(eB) & amaskB;
                    }
                }
                int sw0 = (jp0 + r)     ^ (q << 2);
                int sw1 = (jp0 + 4 + r) ^ (q << 2);
#pragma unroll
                for (int nt = 0; nt < 4; nt++) {
                    int base = (nt*8 + q) * 512;
                    uint32_t bh0 = WhHi[base + sw0], bh1 = WhHi[base + sw1];
#pragma unroll
                    for (int f = 0; f < 2; f++)
                        mma16h(acc[f][nt], Ah[f], bh0, bh1);
                }
#pragma unroll
                for (int f = 0; f < 2; f++)
                    mma16h(accz[f], Ah[f], ONES16, ONES16);
            }
        }
    }

#pragma unroll
    for (int f = 0; f < 2; f++) {
#pragma unroll
        for (int rs = 0; rs < 2; rs++) {
            float inv = 1.f / accz[f][2*rs];
            int node = row0 + warp*32 + q + 16*f + 8*rs;
            unsigned long long o2[6];
#pragma unroll
            for (int i = 0; i < 6; i++) o2[i] = 0ull;
#pragma unroll
            for (int nt = 0; nt < 4; nt++) {
                float xx = eluf(acc[f][nt][2*rs]*inv);
                float yy = eluf(acc[f][nt][2*rs+1]*inv);
                unsigned long long x2 = pack2(xx), y2 = pack2(yy);
                const unsigned long long* w0 = (const unsigned long long*)(Wo + (nt*8 + 2*r)*NP);
                const unsigned long long* w1 = (const unsigned long long*)(Wo + (nt*8 + 2*r + 1)*NP);
#pragma unroll
                for (int i = 0; i < 6; i++) {
                    o2[i] = ffma2(x2, w0[i], o2[i]);
                    o2[i] = ffma2(y2, w1[i], o2[i]);
                }
            }
#pragma unroll
            for (int i = 0; i < 6; i++) {
                o2[i] = addf2(o2[i], __shfl_xor_sync(0xffffffffu, o2[i], 1));
                o2[i] = addf2(o2[i], __shfl_xor_sync(0xffffffffu, o2[i], 2));
            }
            if (r == 0) {
                float* dst = g_Wh2p + (((size_t)h*B + b)*NN + node)*NP;
                float2 v0 = unpk2(o2[0]), v1 = unpk2(o2[1]), v2 = unpk2(o2[2]);
                float2 v3 = unpk2(o2[3]), v4 = unpk2(o2[4]), v5 = unpk2(o2[5]);
                *(float4*)dst       = make_float4(v0.x, v0.y, v1.x, v1.y);
                *(float4*)(dst + 4) = make_float4(v2.x, v2.y, v3.x, v3.y);
                *(float4*)(dst + 8) = make_float4(v4.x, v4.y, v5.x, v5.y);
            }
        }
    }
}

// ---------------- K3: layer-2 via mma; 256 thr (2 row-tiles x 4 jsegs), 2 CTA/SM ----------------
__global__ void __launch_bounds__(256, 2) k_attn2_m(float* __restrict__ out,
                                                    const float* __restrict__ ao_src,
                                                    const float* __restrict__ ao_dst) {
    extern __shared__ float sm[];
    uint32_t* Vh   = (uint32_t*)sm;              // [16][512] f16x2 pairs (cols 12-15 zero)
    uint32_t* gd_h = Vh + 16*512;                // [512] half2 of gd*LOG2E
    float* gs_s    = (float*)(gd_h + 512);       // [1024]
    float* red     = gs_s + NN;                  // [3][2][32][21]

    int tid = threadIdx.x, warp = tid >> 5, lane = tid & 31;
    int r = lane & 3, q = lane >> 2;
    int b = blockIdx.x >> 4, chunk = blockIdx.x & 15;
    int row0 = chunk*64;

    // stage: sum 4 head slices for node pairs, pack to f16, compute gs/gd
    for (int jp = tid; jp < NN/2; jp += 256) {
        float va[24];
#pragma unroll
        for (int i = 0; i < 24; i++) va[i] = 0.f;
#pragma unroll
        for (int hh = 0; hh < HEADS; hh++) {
            const float4* vp = (const float4*)(g_Wh2p + (((size_t)hh*B + b)*NN + 2*jp)*NP);
#pragma unroll
            for (int i = 0; i < 6; i++) {
                float4 p = __ldg(vp + i);
                va[4*i] += p.x; va[4*i+1] += p.y; va[4*i+2] += p.z; va[4*i+3] += p.w;
            }
        }
#pragma unroll
        for (int c = 0; c < NP; c++)
            Vh[c*512 + (jp ^ ((c & 7) << 2))] = pk16(va[c], va[12 + c]);
#pragma unroll
        for (int c = NP; c < 16; c++)
            Vh[c*512 + (jp ^ ((c & 7) << 2))] = 0u;
        float gs0 = 0.f, gd0 = 0.f, gs1 = 0.f, gd1 = 0.f;
#pragma unroll
        for (int p = 0; p < NP; p++) {
            float as = __ldg(ao_src + p), ad = __ldg(ao_dst + p);
            gs0 += va[p]*as;      gd0 += va[p]*ad;
            gs1 += va[12 + p]*as; gd1 += va[12 + p]*ad;
        }
        gs_s[2*jp]     = gs0 * LOG2E;
        gs_s[2*jp + 1] = gs1 * LOG2E;
        gd_h[jp] = pk16(gd0 * LOG2E, gd1 * LOG2E);
    }
    __syncthreads();

    int rw = warp & 1, jseg = warp >> 1;
    const uint4* mp4[4];
    uint32_t fs2h[4];
#pragma unroll
    for (int t = 0; t < 4; t++) {
        int row = row0 + rw*32 + q + 8*t;
        mp4[t] = (const uint4*)(g_mask + (size_t)row*32);
        float fv = gs_s[row];
        fs2h[t] = pk16(fv, fv);
    }
    const uint32_t C02H = 0x32663266u;

    float acc[2][2][4];
    float accz[2][4];
#pragma unroll
    for (int f = 0; f < 2; f++) {
#pragma unroll
        for (int nt = 0; nt < 2; nt++)
#pragma unroll
            for (int i = 0; i < 4; i++) acc[f][nt][i] = 0.f;
#pragma unroll
        for (int i = 0; i < 4; i++) accz[f][i] = 0.f;
    }

#pragma unroll 1
    for (int gi = 0; gi < 2; gi++) {
        int gg = jseg*2 + gi;
        uint4 m4[4];
#pragma unroll
        for (int t = 0; t < 4; t++) m4[t] = __ldg(mp4[t] + gg);
#pragma unroll
        for (int sub = 0; sub < 4; sub++) {
            unsigned mw[4];
#pragma unroll
            for (int t = 0; t < 4; t++)
                mw[t] = (sub == 0) ? m4[t].x : (sub == 1) ? m4[t].y : (sub == 2) ? m4[t].z : m4[t].w;
            int g = gg*4 + sub;
            uint32_t us[4], vs[4];
#pragma unroll
            for (int t = 0; t < 4; t++) {
                us[t] = mw[t] << (7 - 2*r);
                vs[t] = mw[t] << (6 - 2*r);
            }
#pragma unroll
            for (int ck = 0; ck < 2; ck++) {
                int jp0 = g*16 + ck*8;
                uint32_t fdA = gd_h[jp0 + r];
                uint32_t fdB = gd_h[jp0 + 4 + r];
                uint32_t selA = ck ? 0xEEAAu : 0xCC88u;
                uint32_t selB = ck ? 0xFFBBu : 0xDD99u;
                uint32_t Ah[2][4];
#pragma unroll
                for (int f = 0; f < 2; f++) {
#pragma unroll
                    for (int hh = 0; hh < 2; hh++) {
                        int t = 2*f + hh;
                        uint32_t amaskA = prmt_sr(us[t], vs[t], selA);
                        uint32_t amaskB = prmt_sr(us[t], vs[t], selB);
                        uint32_t eA = hadd2u(fs2h[t], fdA);
                        uint32_t eB = hadd2u(fs2h[t], fdB);
                        eA = hmax2u(eA, hmul2u(eA, C02H));
                        eB = hmax2u(eB, hmul2u(eB, C02H));
                        Ah[f][hh]     = ex2h2(eA) & amaskA;
                        Ah[f][2 + hh] = ex2h2(eB) & amaskB;
                    }
                }
                int sw0 = (jp0 + r)     ^ (q << 2);
                int sw1 = (jp0 + 4 + r) ^ (q << 2);
#pragma unroll
                for (int nt = 0; nt < 2; nt++) {
                    int base = (nt*8 + q) * 512;
                    uint32_t bh0 = Vh[base + sw0], bh1 = Vh[base + sw1];
#pragma unroll
                    for (int f = 0; f < 2; f++)
                        mma16h(acc[f][nt], Ah[f], bh0, bh1);
                }
#pragma unroll
                for (int f = 0; f < 2; f++)
                    mma16h(accz[f], Ah[f], ONES16, ONES16);
            }
        }
    }

    // cross-jseg reduction through smem (stride 21 -> conflict-free)
    if (jseg > 0) {
        float* dp = red + (((jseg - 1)*2 + rw)*32 + lane)*21;
        int c = 0;
#pragma unroll
        for (int f = 0; f < 2; f++)
#pragma unroll
            for (int nt = 0; nt < 2; nt++)
#pragma unroll
                for (int i = 0; i < 4; i++) dp[c++] = acc[f][nt][i];
        dp[16] = accz[0][0]; dp[17] = accz[0][2];
        dp[18] = accz[1][0]; dp[19] = accz[1][2];
    }
    __syncthreads();
    if (jseg == 0) {
        float z00 = accz[0][0], z02 = accz[0][2], z10 = accz[1][0], z12 = accz[1][2];
#pragma unroll
        for (int s = 0; s < 3; s++) {
            const float* sp = red + ((s*2 + rw)*32 + lane)*21;
            int c = 0;
#pragma unroll
            for (int f = 0; f < 2; f++)
#pragma unroll
                for (int nt = 0; nt < 2; nt++)
#pragma unroll
                    for (int i = 0; i < 4; i++) acc[f][nt][i] += sp[c++];
            z00 += sp[16]; z02 += sp[17]; z10 += sp[18]; z12 += sp[19];
        }
        float zz[2][2] = {{z00, z02}, {z10, z12}};
#pragma unroll
        for (int f = 0; f < 2; f++) {
#pragma unroll
            for (int hh = 0; hh < 2; hh++) {
                int row = row0 + rw*32 + q + 16*f + 8*hh;
                float inv = 1.f / zz[f][hh];
#pragma unroll
                for (int nt = 0; nt < 2; nt++) {
                    int col = nt*8 + 2*r;
                    if (nt == 0 || r < 2) {
                        float2 v;
                        v.x = eluf(acc[f][nt][2*hh]*inv);
                        v.y = eluf(acc[f][nt][2*hh + 1]*inv);
                        *(float2*)(out + (size_t)b*NN*NP + (size_t)row*NP + col) = v;
                    }
                }
            }
        }
    }
}

// ---------------- launch ----------------
extern "C" void kernel_launch(void* const* d_in, const int* in_sizes, int n_in,
                              void* d_out, int out_size) {
    const float* x         = (const float*)d_in[0];
    const int*   adj       = (const int*)  d_in[1];
    const float* W         = (const float*)d_in[2];
    const float* a_src     = (const float*)d_in[3];
    const float* a_dst     = (const float*)d_in[4];
    const float* W_out     = (const float*)d_in[5];
    const float* a_out_src = (const float*)d_in[6];
    const float* a_out_dst = (const float*)d_in[7];
    float* out = (float*)d_out;

    int smem1 = (32*512 + 512 + NHID*NP) * (int)sizeof(float);            // 69120 B
    int smem2 = (16*512 + 512 + NN + 3*2*32*21) * (int)sizeof(float);     // 55040 B
    cudaFuncSetAttribute(k_attn1_f, cudaFuncAttributeMaxDynamicSharedMemorySize, smem1);
    cudaFuncSetAttribute(k_attn2_m, cudaFuncAttributeMaxDynamicSharedMemorySize, smem2);

    k_mask<<<NN, NN>>>(adj);
    k_wh<<<dim3(B*HEADS, NN/256), 256>>>(x, W, a_src, a_dst);
    k_attn1_f<<<B*HEADS*4, 256, smem1>>>(W_out);
    k_attn2_m<<<B*16, 256, smem2>>>(out, a_out_src, a_out_dst);
}

// round 16
// speedup vs baseline: 1.0850x; 1.0850x over previous
#include <cuda_runtime.h>
#include <cuda_fp16.h>
#include <cstdint>

#define B 16
#define NN 1024
#define NF 16
#define NHID 32
#define HEADS 4
#define NP 12
#define LOG2E 1.4426950408889634f
#define ONES16 0x3C003C00u

__device__ float    g_Wh[B*HEADS*NN*NHID];
__device__ float    g_fsrc[B*HEADS*NN];
__device__ float    g_fdst[B*HEADS*NN];
__device__ unsigned g_mask[NN*NN/32];
__device__ float    g_Wh2p[HEADS*B*NN*NP];   // per-head partial projections

__device__ __forceinline__ float ex2f(float x) {
    float y; asm("ex2.approx.f32 %0, %1;" : "=f"(y) : "f"(x)); return y;
}
__device__ __forceinline__ float eluf(float v) { return v > 0.f ? v : (ex2f(v*LOG2E) - 1.f); }

__device__ __forceinline__ unsigned long long ffma2(unsigned long long a, unsigned long long b,
                                                    unsigned long long c) {
    unsigned long long d;
    asm("fma.rn.f32x2 %0, %1, %2, %3;" : "=l"(d) : "l"(a), "l"(b), "l"(c));
    return d;
}
__device__ __forceinline__ unsigned long long addf2(unsigned long long a, unsigned long long b) {
    unsigned long long d;
    asm("add.rn.f32x2 %0, %1, %2;" : "=l"(d) : "l"(a), "l"(b));
    return d;
}
__device__ __forceinline__ unsigned long long pack2(float x) {
    unsigned long long d;
    asm("mov.b64 %0, {%1, %2};" : "=l"(d) : "f"(x), "f"(x));
    return d;
}
__device__ __forceinline__ float2 unpk2(unsigned long long v) {
    float2 f;
    asm("mov.b64 {%0, %1}, %2;" : "=f"(f.x), "=f"(f.y) : "l"(v));
    return f;
}
__device__ __forceinline__ uint32_t pk16(float a, float b) {
    uint32_t h;
    asm("cvt.rn.f16x2.f32 %0, %1, %2;" : "=r"(h) : "f"(b), "f"(a));
    return h;
}
__device__ __forceinline__ uint32_t hadd2u(uint32_t a, uint32_t b) {
    uint32_t d; asm("add.rn.f16x2 %0, %1, %2;" : "=r"(d) : "r"(a), "r"(b)); return d;
}
__device__ __forceinline__ uint32_t hmul2u(uint32_t a, uint32_t b) {
    uint32_t d; asm("mul.rn.f16x2 %0, %1, %2;" : "=r"(d) : "r"(a), "r"(b)); return d;
}
__device__ __forceinline__ uint32_t hmax2u(uint32_t a, uint32_t b) {
    uint32_t d; asm("max.f16x2 %0, %1, %2;" : "=r"(d) : "r"(a), "r"(b)); return d;
}
__device__ __forceinline__ uint32_t ex2h2(uint32_t a) {
    uint32_t d; asm("ex2.approx.f16x2 %0, %1;" : "=r"(d) : "r"(a)); return d;
}
// raw PTX prmt: generic mode honors per-nibble msb sign-replicate (__byte_perm does NOT)
__device__ __forceinline__ uint32_t prmt_sr(uint32_t a, uint32_t b, uint32_t sel) {
    uint32_t d; asm("prmt.b32 %0, %1, %2, %3;" : "=r"(d) : "r"(a), "r"(b), "r"(sel)); return d;
}
__device__ __forceinline__ void mma16h(float* d, const uint32_t* a, uint32_t b0, uint32_t b1) {
    asm("mma.sync.aligned.m16n8k16.row.col.f32.f16.f16.f32 "
        "{%0,%1,%2,%3},{%4,%5,%6,%7},{%8,%9},{%0,%1,%2,%3};"
        : "+f"(d[0]), "+f"(d[1]), "+f"(d[2]), "+f"(d[3])
        : "r"(a[0]), "r"(a[1]), "r"(a[2]), "r"(a[3]), "r"(b0), "r"(b1));
}

// ---------------- K0: adjacency -> bitmask ----------------
__global__ void k_mask(const int* __restrict__ adj) {
    int i = blockIdx.x, j = threadIdx.x;
    unsigned bal = __ballot_sync(0xffffffffu, adj[i*NN + j] > 0);
    if ((j & 31) == 0) g_mask[i*32 + (j >> 5)] = bal;
}

// ---------------- K1: Wh = x@W (f32x2), 2-way k-split, f_src/f_dst via partner shfl ----------------
__global__ void k_wh(const float* __restrict__ x, const float* __restrict__ W,
                     const float* __restrict__ a_src, const float* __restrict__ a_dst) {
    __shared__ float Ws[NF*NHID], as_s[NHID], ad_s[NHID];
    int bh = blockIdx.x, b = bh >> 2, h = bh & 3, tid = threadIdx.x;
    for (int i = tid; i < NF*NHID; i += 256) Ws[i] = W[h*NF*NHID + i];
    if (tid < NHID) { as_s[tid] = a_src[h*NHID + tid]; ad_s[tid] = a_dst[h*NHID + tid]; }
    __syncthreads();
    int gidx = blockIdx.y*256 + tid;
    int n = gidx >> 1, khalf = gidx & 1;       // partner threads tid, tid^1
    const float4* xp = (const float4*)(x + ((size_t)b*NN + n)*NF);
    float xf[NF];
#pragma unroll
    for (int i = 0; i < NF/4; i++) {
        float4 v = __ldg(xp + i);
        xf[4*i] = v.x; xf[4*i+1] = v.y; xf[4*i+2] = v.z; xf[4*i+3] = v.w;
    }
    unsigned long long wh2[8];                 // 16 k-columns
#pragma unroll
    for (int k2 = 0; k2 < 8; k2++) wh2[k2] = 0ull;
#pragma unroll
    for (int f = 0; f < NF; f++) {
        unsigned long long xv2 = pack2(xf[f]);
        const unsigned long long* wr = (const unsigned long long*)(Ws + f*NHID) + khalf*8;
#pragma unroll
        for (int k2 = 0; k2 < 8; k2++) wh2[k2] = ffma2(xv2, wr[k2], wh2[k2]);
    }
    unsigned long long fs2 = 0ull, fd2 = 0ull;
    const unsigned long long* as2 = (const unsigned long long*)as_s + khalf*8;
    const unsigned long long* ad2 = (const unsigned long long*)ad_s + khalf*8;
#pragma unroll
    for (int k2 = 0; k2 < 8; k2++) {
        fs2 = ffma2(wh2[k2], as2[k2], fs2);
        fd2 = ffma2(wh2[k2], ad2[k2], fd2);
    }
    float2 fsp = unpk2(fs2), fdp = unpk2(fd2);
    float fs = fsp.x + fsp.y, fd = fdp.x + fdp.y;
    fs += __shfl_xor_sync(0xffffffffu, fs, 1);
    fd += __shfl_xor_sync(0xffffffffu, fd, 1);
    unsigned long long* op = (unsigned long long*)(g_Wh + ((size_t)bh*NN + n)*NHID) + khalf*8;
#pragma unroll
    for (int k2 = 0; k2 < 8; k2++) op[k2] = wh2[k2];
    if (khalf == 0) {
        g_fsrc[bh*NN + n] = fs;
        g_fdst[bh*NN + n] = fd;
    }
}

// ---------------- K2: fused GAT layer 1 + h@W_out partial (per-head slice stores) ----------------
__global__ void __launch_bounds__(512, 1) k_attn1_f(const float* __restrict__ W_out) {
    extern __shared__ float sm[];
    uint32_t* WhHi = (uint32_t*)sm;              // [32][512] f16x2 (j even/odd pairs)
    uint32_t* fd_h = WhHi + 32*512;              // [512] half2 of fd*LOG2E pairs
    float* Wo = (float*)(fd_h + 512);            // [32][12] W_out slice for this head

    int tid = threadIdx.x, warp = tid >> 5, lane = tid & 31;
    int r = lane & 3, q = lane >> 2;
    int bh = blockIdx.x >> 1, half = blockIdx.x & 1;
    int b = bh >> 2, h = bh & 3, row0 = half*512;

    const float* Whg = g_Wh + (size_t)bh*NN*NHID;
    for (int idx = tid; idx < NN*NHID/2; idx += 512) {
        int jp = idx >> 5, k = idx & 31;
        float w0 = Whg[(2*jp)*NHID + k];
        float w1 = Whg[(2*jp+1)*NHID + k];
        int jsw = jp ^ ((k & 7) << 2);
        WhHi[k*512 + jsw] = pk16(w0, w1);
    }
    {
        const float* fdg = g_fdst + bh*NN;
        for (int jp = tid; jp < NN/2; jp += 512)
            fd_h[jp] = pk16(fdg[2*jp]*LOG2E, fdg[2*jp+1]*LOG2E);
    }
    if (tid < NHID*NP) Wo[tid] = W_out[h*NHID*NP + tid];
    __syncthreads();

    const uint4* mp4[4];
    uint32_t fs2h[4];
#pragma unroll
    for (int t = 0; t < 4; t++) {
        int row = row0 + warp*32 + q + 8*t;
        mp4[t] = (const uint4*)(g_mask + (size_t)row*32);
        float fv = g_fsrc[bh*NN + row] * LOG2E;
        fs2h[t] = pk16(fv, fv);
    }
    const uint32_t C02H = 0x32663266u;

    float acc[2][4][4];
    float accz[2][4];
#pragma unroll
    for (int f = 0; f < 2; f++) {
#pragma unroll
        for (int nt = 0; nt < 4; nt++)
#pragma unroll
            for (int i = 0; i < 4; i++) acc[f][nt][i] = 0.f;
#pragma unroll
        for (int i = 0; i < 4; i++) accz[f][i] = 0.f;
    }

#pragma unroll 1
    for (int gg = 0; gg < 8; gg++) {
        uint4 m4[4];
#pragma unroll
        for (int t = 0; t < 4; t++) m4[t] = __ldg(mp4[t] + gg);
#pragma unroll
        for (int sub = 0; sub < 4; sub++) {
            unsigned mw[4];
#pragma unroll
            for (int t = 0; t < 4; t++)
                mw[t] = (sub == 0) ? m4[t].x : (sub == 1) ? m4[t].y : (sub == 2) ? m4[t].z : m4[t].w;
            int g = gg*4 + sub;
            uint32_t us[4], vs[4];
#pragma unroll
            for (int t = 0; t < 4; t++) {
                us[t] = mw[t] << (7 - 2*r);
                vs[t] = mw[t] << (6 - 2*r);
            }
#pragma unroll
            for (int ck = 0; ck < 2; ck++) {
                int jp0 = g*16 + ck*8;
                uint32_t fdA = fd_h[jp0 + r];
                uint32_t fdB = fd_h[jp0 + 4 + r];
                uint32_t selA = ck ? 0xEEAAu : 0xCC88u;
                uint32_t selB = ck ? 0xFFBBu : 0xDD99u;
                uint32_t Ah[2][4];
#pragma unroll
                for (int f = 0; f < 2; f++) {
#pragma unroll
                    for (int hh = 0; hh < 2; hh++) {
                        int t = 2*f + hh;
                        uint32_t amaskA = prmt_sr(us[t], vs[t], selA);
                        uint32_t amaskB = prmt_sr(us[t], vs[t], selB);
                        uint32_t eA = hadd2u(fs2h[t], fdA);
                        uint32_t eB = hadd2u(fs2h[t], fdB);
                        eA = hmax2u(eA, hmul2u(eA, C02H));
                        eB = hmax2u(eB, hmul2u(eB, C02H));
                        Ah[f][hh]     = ex2h2(eA) & amaskA;
                        Ah[f][2 + hh] = ex2h2(eB) & amaskB;
                    }
                }
                int sw0 = (jp0 + r)     ^ (q << 2);
                int sw1 = (jp0 + 4 + r) ^ (q << 2);
#pragma unroll
                for (int nt = 0; nt < 4; nt++) {
                    int base = (nt*8 + q) * 512;
                    uint32_t bh0 = WhHi[base + sw0], bh1 = WhHi[base + sw1];
#pragma unroll
                    for (int f = 0; f < 2; f++)
                        mma16h(acc[f][nt], Ah[f], bh0, bh1);
                }
#pragma unroll
                for (int f = 0; f < 2; f++)
                    mma16h(accz[f], Ah[f], ONES16, ONES16);
            }
        }
    }

#pragma unroll
    for (int f = 0; f < 2; f++) {
#pragma unroll
        for (int rs = 0; rs < 2; rs++) {
            float inv = 1.f / accz[f][2*rs];
            int node = row0 + warp*32 + q + 16*f + 8*rs;
            unsigned long long o2[6];
#pragma unroll
            for (int i = 0; i < 6; i++) o2[i] = 0ull;
#pragma unroll
            for (int nt = 0; nt < 4; nt++) {
                float xx = eluf(acc[f][nt][2*rs]*inv);
                float yy = eluf(acc[f][nt][2*rs+1]*inv);
                unsigned long long x2 = pack2(xx), y2 = pack2(yy);
                const unsigned long long* w0 = (const unsigned long long*)(Wo + (nt*8 + 2*r)*NP);
                const unsigned long long* w1 = (const unsigned long long*)(Wo + (nt*8 + 2*r + 1)*NP);
#pragma unroll
                for (int i = 0; i < 6; i++) {
                    o2[i] = ffma2(x2, w0[i], o2[i]);
                    o2[i] = ffma2(y2, w1[i], o2[i]);
                }
            }
#pragma unroll
            for (int i = 0; i < 6; i++) {
                o2[i] = addf2(o2[i], __shfl_xor_sync(0xffffffffu, o2[i], 1));
                o2[i] = addf2(o2[i], __shfl_xor_sync(0xffffffffu, o2[i], 2));
            }
            if (r == 0) {
                float* dst = g_Wh2p + (((size_t)h*B + b)*NN + node)*NP;
                float2 v0 = unpk2(o2[0]), v1 = unpk2(o2[1]), v2 = unpk2(o2[2]);
                float2 v3 = unpk2(o2[3]), v4 = unpk2(o2[4]), v5 = unpk2(o2[5]);
                *(float4*)dst       = make_float4(v0.x, v0.y, v1.x, v1.y);
                *(float4*)(dst + 4) = make_float4(v2.x, v2.y, v3.x, v3.y);
                *(float4*)(dst + 8) = make_float4(v4.x, v4.y, v5.x, v5.y);
            }
        }
    }
}

// ---------------- K3: layer-2 via mma (V padded to 16 cols), warp = (row-tile, j-quarter) ----------------
__global__ void __launch_bounds__(512, 1) k_attn2_m(float* __restrict__ out,
                                                    const float* __restrict__ ao_src,
                                                    const float* __restrict__ ao_dst) {
    extern __shared__ float sm[];
    uint32_t* Vh   = (uint32_t*)sm;              // [16][512] f16x2 pairs (cols 12-15 zero)
    uint32_t* gd_h = Vh + 16*512;                // [512] half2 of gd*LOG2E
    float* gs_s    = (float*)(gd_h + 512);       // [1024]
    float* red     = gs_s + NN;                  // [3][4][32][21]

    int tid = threadIdx.x, warp = tid >> 5, lane = tid & 31;
    int r = lane & 3, q = lane >> 2;
    int b = blockIdx.x >> 3, chunk = blockIdx.x & 7;
    int row0 = chunk*128;

    // stage: sum 4 head slices for node pair (2*tid, 2*tid+1), pack to f16, compute gs/gd
    {
        int jp = tid;
        float va[24];
#pragma unroll
        for (int i = 0; i < 24; i++) va[i] = 0.f;
#pragma unroll
        for (int hh = 0; hh < HEADS; hh++) {
            const float4* vp = (const float4*)(g_Wh2p + (((size_t)hh*B + b)*NN + 2*jp)*NP);
#pragma unroll
            for (int i = 0; i < 6; i++) {
                float4 p = __ldg(vp + i);
                va[4*i] += p.x; va[4*i+1] += p.y; va[4*i+2] += p.z; va[4*i+3] += p.w;
            }
        }
#pragma unroll
        for (int c = 0; c < NP; c++)
            Vh[c*512 + (jp ^ ((c & 7) << 2))] = pk16(va[c], va[12 + c]);
#pragma unroll
        for (int c = NP; c < 16; c++)
            Vh[c*512 + (jp ^ ((c & 7) << 2))] = 0u;
        float gs0 = 0.f, gd0 = 0.f, gs1 = 0.f, gd1 = 0.f;
#pragma unroll
        for (int p = 0; p < NP; p++) {
            float as = __ldg(ao_src + p), ad = __ldg(ao_dst + p);
            gs0 += va[p]*as;      gd0 += va[p]*ad;
            gs1 += va[12 + p]*as; gd1 += va[12 + p]*ad;
        }
        gs_s[2*jp]     = gs0 * LOG2E;
        gs_s[2*jp + 1] = gs1 * LOG2E;
        gd_h[jp] = pk16(gd0 * LOG2E, gd1 * LOG2E);
    }
    __syncthreads();

    int rw = warp & 3, jseg = warp >> 2;
    const uint4* mp4[4];
    uint32_t fs2h[4];
#pragma unroll
    for (int t = 0; t < 4; t++) {
        int row = row0 + rw*32 + q + 8*t;
        mp4[t] = (const uint4*)(g_mask + (size_t)row*32);
        float fv = gs_s[row];
        fs2h[t] = pk16(fv, fv);
    }
    const uint32_t C02H = 0x32663266u;

    float acc[2][2][4];
    float accz[2][4];
#pragma unroll
    for (int f = 0; f < 2; f++) {
#pragma unroll
        for (int nt = 0; nt < 2; nt++)
#pragma unroll
            for (int i = 0; i < 4; i++) acc[f][nt][i] = 0.f;
#pragma unroll
        for (int i = 0; i < 4; i++) accz[f][i] = 0.f;
    }

#pragma unroll 1
    for (int gi = 0; gi < 2; gi++) {
        int gg = jseg*2 + gi;
        uint4 m4[4];
#pragma unroll
        for (int t = 0; t < 4; t++) m4[t] = __ldg(mp4[t] + gg);
#pragma unroll
        for (int sub = 0; sub < 4; sub++) {
            unsigned mw[4];
#pragma unroll
            for (int t = 0; t < 4; t++)
                mw[t] = (sub == 0) ? m4[t].x : (sub == 1) ? m4[t].y : (sub == 2) ? m4[t].z : m4[t].w;
            int g = gg*4 + sub;
            uint32_t us[4], vs[4];
#pragma unroll
            for (int t = 0; t < 4; t++) {
                us[t] = mw[t] << (7 - 2*r);
                vs[t] = mw[t] << (6 - 2*r);
            }
#pragma unroll
            for (int ck = 0; ck < 2; ck++) {
                int jp0 = g*16 + ck*8;
                uint32_t fdA = gd_h[jp0 + r];
                uint32_t fdB = gd_h[jp0 + 4 + r];
                uint32_t selA = ck ? 0xEEAAu : 0xCC88u;
                uint32_t selB = ck ? 0xFFBBu : 0xDD99u;
                uint32_t Ah[2][4];
#pragma unroll
                for (int f = 0; f < 2; f++) {
#pragma unroll
                    for (int hh = 0; hh < 2; hh++) {
                        int t = 2*f + hh;
                        uint32_t amaskA = prmt_sr(us[t], vs[t], selA);
                        uint32_t amaskB = prmt_sr(us[t], vs[t], selB);
                        uint32_t eA = hadd2u(fs2h[t], fdA);
                        uint32_t eB = hadd2u(fs2h[t], fdB);
                        eA = hmax2u(eA, hmul2u(eA, C02H));
                        eB = hmax2u(eB, hmul2u(eB, C02H));
                        Ah[f][hh]     = ex2h2(eA) & amaskA;
                        Ah[f][2 + hh] = ex2h2(eB) & amaskB;
                    }
                }
                int sw0 = (jp0 + r)     ^ (q << 2);
                int sw1 = (jp0 + 4 + r) ^ (q << 2);
#pragma unroll
                for (int nt = 0; nt < 2; nt++) {
                    int base = (nt*8 + q) * 512;
                    uint32_t bh0 = Vh[base + sw0], bh1 = Vh[base + sw1];
#pragma unroll
                    for (int f = 0; f < 2; f++)
                        mma16h(acc[f][nt], Ah[f], bh0, bh1);
                }
#pragma unroll
                for (int f = 0; f < 2; f++)
                    mma16h(accz[f], Ah[f], ONES16, ONES16);
            }
        }
    }

    // cross-jseg reduction through smem (stride 21 -> conflict-free)
    if (jseg > 0) {
        float* dp = red + (((jseg - 1)*4 + rw)*32 + lane)*21;
        int c = 0;
#pragma unroll
        for (int f = 0; f < 2; f++)
#pragma unroll
            for (int nt = 0; nt < 2; nt++)
#pragma unroll
                for (int i = 0; i < 4; i++) dp[c++] = acc[f][nt][i];
        dp[16] = accz[0][0]; dp[17] = accz[0][2];
        dp[18] = accz[1][0]; dp[19] = accz[1][2];
    }
    __syncthreads();
    if (jseg == 0) {
        float z00 = accz[0][0], z02 = accz[0][2], z10 = accz[1][0], z12 = accz[1][2];
#pragma unroll
        for (int s = 0; s < 3; s++) {
            const float* sp = red + ((s*4 + rw)*32 + lane)*21;
            int c = 0;
#pragma unroll
            for (int f = 0; f < 2; f++)
#pragma unroll
                for (int nt = 0; nt < 2; nt++)
#pragma unroll
                    for (int i = 0; i < 4; i++) acc[f][nt][i] += sp[c++];
            z00 += sp[16]; z02 += sp[17]; z10 += sp[18]; z12 += sp[19];
        }
        float zz[2][2] = {{z00, z02}, {z10, z12}};
#pragma unroll
        for (int f = 0; f < 2; f++) {
#pragma unroll
            for (int hh = 0; hh < 2; hh++) {
                int row = row0 + rw*32 + q + 16*f + 8*hh;
                float inv = 1.f / zz[f][hh];
#pragma unroll
                for (int nt = 0; nt < 2; nt++) {
                    int col = nt*8 + 2*r;
                    if (nt == 0 || r < 2) {
                        float2 v;
                        v.x = eluf(acc[f][nt][2*hh]*inv);
                        v.y = eluf(acc[f][nt][2*hh + 1]*inv);
                        *(float2*)(out + (size_t)b*NN*NP + (size_t)row*NP + col) = v;
                    }
                }
            }
        }
    }
}

// ---------------- launch ----------------
extern "C" void kernel_launch(void* const* d_in, const int* in_sizes, int n_in,
                              void* d_out, int out_size) {
    const float* x         = (const float*)d_in[0];
    const int*   adj       = (const int*)  d_in[1];
    const float* W         = (const float*)d_in[2];
    const float* a_src     = (const float*)d_in[3];
    const float* a_dst     = (const float*)d_in[4];
    const float* W_out     = (const float*)d_in[5];
    const float* a_out_src = (const float*)d_in[6];
    const float* a_out_dst = (const float*)d_in[7];
    float* out = (float*)d_out;

    int smem1 = (32*512 + 512 + NHID*NP) * (int)sizeof(float);            // 69120 B
    int smem2 = (16*512 + 512 + NN + 3*4*32*21) * (int)sizeof(float);     // 71168 B
    cudaFuncSetAttribute(k_attn1_f, cudaFuncAttributeMaxDynamicSharedMemorySize, smem1);
    cudaFuncSetAttribute(k_attn2_m, cudaFuncAttributeMaxDynamicSharedMemorySize, smem2);

    k_mask<<<NN, NN>>>(adj);
    k_wh<<<dim3(B*HEADS, NN*2/256), 256>>>(x, W, a_src, a_dst);
    k_attn1_f<<<B*HEADS*2, 512, smem1>>>(W_out);
    k_attn2_m<<<B*8, 512, smem2>>>(out, a_out_src, a_out_dst);
}

// round 17
// speedup vs baseline: 1.1322x; 1.0435x over previous
#include <cuda_runtime.h>
#include <cuda_fp16.h>
#include <cstdint>

#define B 16
#define NN 1024
#define NF 16
#define NHID 32
#define HEADS 4
#define NP 12
#define LOG2E 1.4426950408889634f
#define ONES16 0x3C003C00u

__device__ float    g_Wh[B*HEADS*NN*NHID];
__device__ float    g_fsrc[B*HEADS*NN];
__device__ float    g_fdst[B*HEADS*NN];
__device__ unsigned g_mask[NN*NN/32];
__device__ float    g_Wh2p[HEADS*B*NN*NP];   // per-head partial projections

__device__ __forceinline__ float ex2f(float x) {
    float y; asm("ex2.approx.f32 %0, %1;" : "=f"(y) : "f"(x)); return y;
}
__device__ __forceinline__ float eluf(float v) { return v > 0.f ? v : (ex2f(v*LOG2E) - 1.f); }

__device__ __forceinline__ unsigned long long ffma2(unsigned long long a, unsigned long long b,
                                                    unsigned long long c) {
    unsigned long long d;
    asm("fma.rn.f32x2 %0, %1, %2, %3;" : "=l"(d) : "l"(a), "l"(b), "l"(c));
    return d;
}
__device__ __forceinline__ unsigned long long addf2(unsigned long long a, unsigned long long b) {
    unsigned long long d;
    asm("add.rn.f32x2 %0, %1, %2;" : "=l"(d) : "l"(a), "l"(b));
    return d;
}
__device__ __forceinline__ unsigned long long pack2(float x) {
    unsigned long long d;
    asm("mov.b64 %0, {%1, %2};" : "=l"(d) : "f"(x), "f"(x));
    return d;
}
__device__ __forceinline__ float2 unpk2(unsigned long long v) {
    float2 f;
    asm("mov.b64 {%0, %1}, %2;" : "=f"(f.x), "=f"(f.y) : "l"(v));
    return f;
}
__device__ __forceinline__ uint32_t pk16(float a, float b) {
    uint32_t h;
    asm("cvt.rn.f16x2.f32 %0, %1, %2;" : "=r"(h) : "f"(b), "f"(a));
    return h;
}
__device__ __forceinline__ uint32_t hadd2u(uint32_t a, uint32_t b) {
    uint32_t d; asm("add.rn.f16x2 %0, %1, %2;" : "=r"(d) : "r"(a), "r"(b)); return d;
}
__device__ __forceinline__ uint32_t hmul2u(uint32_t a, uint32_t b) {
    uint32_t d; asm("mul.rn.f16x2 %0, %1, %2;" : "=r"(d) : "r"(a), "r"(b)); return d;
}
__device__ __forceinline__ uint32_t hmax2u(uint32_t a, uint32_t b) {
    uint32_t d; asm("max.f16x2 %0, %1, %2;" : "=r"(d) : "r"(a), "r"(b)); return d;
}
__device__ __forceinline__ uint32_t ex2h2(uint32_t a) {
    uint32_t d; asm("ex2.approx.f16x2 %0, %1;" : "=r"(d) : "r"(a)); return d;
}
// raw PTX prmt: generic mode honors per-nibble msb sign-replicate (__byte_perm does NOT)
__device__ __forceinline__ uint32_t prmt_sr(uint32_t a, uint32_t b, uint32_t sel) {
    uint32_t d; asm("prmt.b32 %0, %1, %2, %3;" : "=r"(d) : "r"(a), "r"(b), "r"(sel)); return d;
}
__device__ __forceinline__ void mma16h(float* d, const uint32_t* a, uint32_t b0, uint32_t b1) {
    asm("mma.sync.aligned.m16n8k16.row.col.f32.f16.f16.f32 "
        "{%0,%1,%2,%3},{%4,%5,%6,%7},{%8,%9},{%0,%1,%2,%3};"
        : "+f"(d[0]), "+f"(d[1]), "+f"(d[2]), "+f"(d[3])
        : "r"(a[0]), "r"(a[1]), "r"(a[2]), "r"(a[3]), "r"(b0), "r"(b1));
}

// ---------------- K1: Wh = x@W (f32x2, 2-way k-split) + fused mask packing ----------------
__global__ void k_wh(const float* __restrict__ x, const float* __restrict__ W,
                     const float* __restrict__ a_src, const float* __restrict__ a_dst,
                     const int* __restrict__ adj) {
    __shared__ float Ws[NF*NHID], as_s[NHID], ad_s[NHID];
    int bh = blockIdx.x, b = bh >> 2, h = bh & 3, tid = threadIdx.x;
    int lane = tid & 31;
    for (int i = tid; i < NF*NHID; i += 256) Ws[i] = W[h*NF*NHID + i];
    if (tid < NHID) { as_s[tid] = a_src[h*NHID + tid]; ad_s[tid] = a_dst[h*NHID + tid]; }
    __syncthreads();
    int gidx = blockIdx.y*256 + tid;
    int n = gidx >> 1, khalf = gidx & 1;
    const float4* xp = (const float4*)(x + ((size_t)b*NN + n)*NF);
    float xf[NF];
#pragma unroll
    for (int i = 0; i < NF/4; i++) {
        float4 v = __ldg(xp + i);
        xf[4*i] = v.x; xf[4*i+1] = v.y; xf[4*i+2] = v.z; xf[4*i+3] = v.w;
    }
    unsigned long long wh2[8];
#pragma unroll
    for (int k2 = 0; k2 < 8; k2++) wh2[k2] = 0ull;
#pragma unroll
    for (int f = 0; f < NF; f++) {
        unsigned long long xv2 = pack2(xf[f]);
        const unsigned long long* wr = (const unsigned long long*)(Ws + f*NHID) + khalf*8;
#pragma unroll
        for (int k2 = 0; k2 < 8; k2++) wh2[k2] = ffma2(xv2, wr[k2], wh2[k2]);
    }
    unsigned long long fs2 = 0ull, fd2 = 0ull;
    const unsigned long long* as2 = (const unsigned long long*)as_s + khalf*8;
    const unsigned long long* ad2 = (const unsigned long long*)ad_s + khalf*8;
#pragma unroll
    for (int k2 = 0; k2 < 8; k2++) {
        fs2 = ffma2(wh2[k2], as2[k2], fs2);
        fd2 = ffma2(wh2[k2], ad2[k2], fd2);
    }
    float2 fsp = unpk2(fs2), fdp = unpk2(fd2);
    float fs = fsp.x + fsp.y, fd = fdp.x + fdp.y;
    fs += __shfl_xor_sync(0xffffffffu, fs, 1);
    fd += __shfl_xor_sync(0xffffffffu, fd, 1);
    unsigned long long* op = (unsigned long long*)(g_Wh + ((size_t)bh*NN + n)*NHID) + khalf*8;
#pragma unroll
    for (int k2 = 0; k2 < 8; k2++) op[k2] = wh2[k2];
    if (khalf == 0) {
        g_fsrc[bh*NN + n] = fs;
        g_fdst[bh*NN + n] = fd;
    }

    // fused adjacency bitmask packing: 4096 warps x 8 row-word tasks = 32768 words
    int wgid = (bh*(int)gridDim.y + blockIdx.y)*8 + (tid >> 5);
#pragma unroll
    for (int it = 0; it < 8; it++) {
        int task = wgid*8 + it;
        int i = task >> 5, jw = task & 31;
        unsigned bal = __ballot_sync(0xffffffffu, adj[(size_t)i*NN + jw*32 + lane] > 0);
        if (lane == 0) g_mask[i*32 + jw] = bal;
    }
}

// ---------------- K2: fused GAT layer 1 + h@W_out partial (B-fragments preloaded) ----------------
__global__ void __launch_bounds__(512, 1) k_attn1_f(const float* __restrict__ W_out) {
    extern __shared__ float sm[];
    uint32_t* WhHi = (uint32_t*)sm;              // [32][512] f16x2 (j even/odd pairs)
    uint32_t* fd_h = WhHi + 32*512;              // [512] half2 of fd*LOG2E pairs
    float* Wo = (float*)(fd_h + 512);            // [32][12] W_out slice for this head

    int tid = threadIdx.x, warp = tid >> 5, lane = tid & 31;
    int r = lane & 3, q = lane >> 2;
    int bh = blockIdx.x >> 1, half = blockIdx.x & 1;
    int b = bh >> 2, h = bh & 3, row0 = half*512;

    const float* Whg = g_Wh + (size_t)bh*NN*NHID;
    for (int idx = tid; idx < NN*NHID/2; idx += 512) {
        int jp = idx >> 5, k = idx & 31;
        float w0 = Whg[(2*jp)*NHID + k];
        float w1 = Whg[(2*jp+1)*NHID + k];
        int jsw = jp ^ ((k & 7) << 2);
        WhHi[k*512 + jsw] = pk16(w0, w1);
    }
    {
        const float* fdg = g_fdst + bh*NN;
        for (int jp = tid; jp < NN/2; jp += 512)
            fd_h[jp] = pk16(fdg[2*jp]*LOG2E, fdg[2*jp+1]*LOG2E);
    }
    if (tid < NHID*NP) Wo[tid] = W_out[h*NHID*NP + tid];
    __syncthreads();

    const uint4* mp4[4];
    uint32_t fs2h[4];
#pragma unroll
    for (int t = 0; t < 4; t++) {
        int row = row0 + warp*32 + q + 8*t;
        mp4[t] = (const uint4*)(g_mask + (size_t)row*32);
        float fv = g_fsrc[bh*NN + row] * LOG2E;
        fs2h[t] = pk16(fv, fv);
    }
    const uint32_t C02H = 0x32663266u;

    float acc[2][4][4];
    float accz[2][4];
#pragma unroll
    for (int f = 0; f < 2; f++) {
#pragma unroll
        for (int nt = 0; nt < 4; nt++)
#pragma unroll
            for (int i = 0; i < 4; i++) acc[f][nt][i] = 0.f;
#pragma unroll
        for (int i = 0; i < 4; i++) accz[f][i] = 0.f;
    }

#pragma unroll 1
    for (int gg = 0; gg < 8; gg++) {
        uint4 m4[4];
#pragma unroll
        for (int t = 0; t < 4; t++) m4[t] = __ldg(mp4[t] + gg);
#pragma unroll
        for (int sub = 0; sub < 4; sub++) {
            unsigned mw[4];
#pragma unroll
            for (int t = 0; t < 4; t++)
                mw[t] = (sub == 0) ? m4[t].x : (sub == 1) ? m4[t].y : (sub == 2) ? m4[t].z : m4[t].w;
            int g = gg*4 + sub;
            uint32_t us[4], vs[4];
#pragma unroll
            for (int t = 0; t < 4; t++) {
                us[t] = mw[t] << (7 - 2*r);
                vs[t] = mw[t] << (6 - 2*r);
            }
#pragma unroll
            for (int ck = 0; ck < 2; ck++) {
                int jp0 = g*16 + ck*8;
                // hoisted loads: B fragments + fd pairs first, hide LDS latency under score math
                int sw0 = (jp0 + r)     ^ (q << 2);
                int sw1 = (jp0 + 4 + r) ^ (q << 2);
                uint32_t Bf[4][2];
#pragma unroll
                for (int nt = 0; nt < 4; nt++) {
                    int base = (nt*8 + q) * 512;
                    Bf[nt][0] = WhHi[base + sw0];
                    Bf[nt][1] = WhHi[base + sw1];
                }
                uint32_t fdA = fd_h[jp0 + r];
                uint32_t fdB = fd_h[jp0 + 4 + r];
                uint32_t selA = ck ? 0xEEAAu : 0xCC88u;
                uint32_t selB = ck ? 0xFFBBu : 0xDD99u;
                uint32_t Ah[2][4];
#pragma unroll
                for (int f = 0; f < 2; f++) {
#pragma unroll
                    for (int hh = 0; hh < 2; hh++) {
                        int t = 2*f + hh;
                        uint32_t amaskA = prmt_sr(us[t], vs[t], selA);
                        uint32_t amaskB = prmt_sr(us[t], vs[t], selB);
                        uint32_t eA = hadd2u(fs2h[t], fdA);
                        uint32_t eB = hadd2u(fs2h[t], fdB);
                        eA = hmax2u(eA, hmul2u(eA, C02H));
                        eB = hmax2u(eB, hmul2u(eB, C02H));
                        Ah[f][hh]     = ex2h2(eA) & amaskA;
                        Ah[f][2 + hh] = ex2h2(eB) & amaskB;
                    }
                }
#pragma unroll
                for (int nt = 0; nt < 4; nt++) {
#pragma unroll
                    for (int f = 0; f < 2; f++)
                        mma16h(acc[f][nt], Ah[f], Bf[nt][0], Bf[nt][1]);
                }
#pragma unroll
                for (int f = 0; f < 2; f++)
                    mma16h(accz[f], Ah[f], ONES16, ONES16);
            }
        }
    }

#pragma unroll
    for (int f = 0; f < 2; f++) {
#pragma unroll
        for (int rs = 0; rs < 2; rs++) {
            float inv = 1.f / accz[f][2*rs];
            int node = row0 + warp*32 + q + 16*f + 8*rs;
            unsigned long long o2[6];
#pragma unroll
            for (int i = 0; i < 6; i++) o2[i] = 0ull;
#pragma unroll
            for (int nt = 0; nt < 4; nt++) {
                float xx = eluf(acc[f][nt][2*rs]*inv);
                float yy = eluf(acc[f][nt][2*rs+1]*inv);
                unsigned long long x2 = pack2(xx), y2 = pack2(yy);
                const unsigned long long* w0 = (const unsigned long long*)(Wo + (nt*8 + 2*r)*NP);
                const unsigned long long* w1 = (const unsigned long long*)(Wo + (nt*8 + 2*r + 1)*NP);
#pragma unroll
                for (int i = 0; i < 6; i++) {
                    o2[i] = ffma2(x2, w0[i], o2[i]);
                    o2[i] = ffma2(y2, w1[i], o2[i]);
                }
            }
#pragma unroll
            for (int i = 0; i < 6; i++) {
                o2[i] = addf2(o2[i], __shfl_xor_sync(0xffffffffu, o2[i], 1));
                o2[i] = addf2(o2[i], __shfl_xor_sync(0xffffffffu, o2[i], 2));
            }
            if (r == 0) {
                float* dst = g_Wh2p + (((size_t)h*B + b)*NN + node)*NP;
                float2 v0 = unpk2(o2[0]), v1 = unpk2(o2[1]), v2 = unpk2(o2[2]);
                float2 v3 = unpk2(o2[3]), v4 = unpk2(o2[4]), v5 = unpk2(o2[5]);
                *(float4*)dst       = make_float4(v0.x, v0.y, v1.x, v1.y);
                *(float4*)(dst + 4) = make_float4(v2.x, v2.y, v3.x, v3.y);
                *(float4*)(dst + 8) = make_float4(v4.x, v4.y, v5.x, v5.y);
            }
        }
    }
}

// ---------------- K3: layer-2 via mma (V padded to 16 cols), warp = (row-tile, j-quarter) ----------------
__global__ void __launch_bounds__(512, 1) k_attn2_m(float* __restrict__ out,
                                                    const float* __restrict__ ao_src,
                                                    const float* __restrict__ ao_dst) {
    extern __shared__ float sm[];
    uint32_t* Vh   = (uint32_t*)sm;              // [16][512] f16x2 pairs (cols 12-15 zero)
    uint32_t* gd_h = Vh + 16*512;                // [512] half2 of gd*LOG2E
    float* gs_s    = (float*)(gd_h + 512);       // [1024]
    float* red     = gs_s + NN;                  // [3][4][32][21]

    int tid = threadIdx.x, warp = tid >> 5, lane = tid & 31;
    int r = lane & 3, q = lane >> 2;
    int b = blockIdx.x >> 3, chunk = blockIdx.x & 7;
    int row0 = chunk*128;

    {
        int jp = tid;
        float va[24];
#pragma unroll
        for (int i = 0; i < 24; i++) va[i] = 0.f;
#pragma unroll
        for (int hh = 0; hh < HEADS; hh++) {
            const float4* vp = (const float4*)(g_Wh2p + (((size_t)hh*B + b)*NN + 2*jp)*NP);
#pragma unroll
            for (int i = 0; i < 6; i++) {
                float4 p = __ldg(vp + i);
                va[4*i] += p.x; va[4*i+1] += p.y; va[4*i+2] += p.z; va[4*i+3] += p.w;
            }
        }
#pragma unroll
        for (int c = 0; c < NP; c++)
            Vh[c*512 + (jp ^ ((c & 7) << 2))] = pk16(va[c], va[12 + c]);
#pragma unroll
        for (int c = NP; c < 16; c++)
            Vh[c*512 + (jp ^ ((c & 7) << 2))] = 0u;
        float gs0 = 0.f, gd0 = 0.f, gs1 = 0.f, gd1 = 0.f;
#pragma unroll
        for (int p = 0; p < NP; p++) {
            float as = __ldg(ao_src + p), ad = __ldg(ao_dst + p);
            gs0 += va[p]*as;      gd0 += va[p]*ad;
            gs1 += va[12 + p]*as; gd1 += va[12 + p]*ad;
        }
        gs_s[2*jp]     = gs0 * LOG2E;
        gs_s[2*jp + 1] = gs1 * LOG2E;
        gd_h[jp] = pk16(gd0 * LOG2E, gd1 * LOG2E);
    }
    __syncthreads();

    int rw = warp & 3, jseg = warp >> 2;
    const uint4* mp4[4];
    uint32_t fs2h[4];
#pragma unroll
    for (int t = 0; t < 4; t++) {
        int row = row0 + rw*32 + q + 8*t;
        mp4[t] = (const uint4*)(g_mask + (size_t)row*32);
        float fv = gs_s[row];
        fs2h[t] = pk16(fv, fv);
    }
    const uint32_t C02H = 0x32663266u;

    float acc[2][2][4];
    float accz[2][4];
#pragma unroll
    for (int f = 0; f < 2; f++) {
#pragma unroll
        for (int nt = 0; nt < 2; nt++)
#pragma unroll
            for (int i = 0; i < 4; i++) acc[f][nt][i] = 0.f;
#pragma unroll
        for (int i = 0; i < 4; i++) accz[f][i] = 0.f;
    }

#pragma unroll 1
    for (int gi = 0; gi < 2; gi++) {
        int gg = jseg*2 + gi;
        uint4 m4[4];
#pragma unroll
        for (int t = 0; t < 4; t++) m4[t] = __ldg(mp4[t] + gg);
#pragma unroll
        for (int sub = 0; sub < 4; sub++) {
            unsigned mw[4];
#pragma unroll
            for (int t = 0; t < 4; t++)
                mw[t] = (sub == 0) ? m4[t].x : (sub == 1) ? m4[t].y : (sub == 2) ? m4[t].z : m4[t].w;
            int g = gg*4 + sub;
            uint32_t us[4], vs[4];
#pragma unroll
            for (int t = 0; t < 4; t++) {
                us[t] = mw[t] << (7 - 2*r);
                vs[t] = mw[t] << (6 - 2*r);
            }
#pragma unroll
            for (int ck = 0; ck < 2; ck++) {
                int jp0 = g*16 + ck*8;
                int sw0 = (jp0 + r)     ^ (q << 2);
                int sw1 = (jp0 + 4 + r) ^ (q << 2);
                uint32_t Bf[2][2];
#pragma unroll
                for (int nt = 0; nt < 2; nt++) {
                    int base = (nt*8 + q) * 512;
                    Bf[nt][0] = Vh[base + sw0];
                    Bf[nt][1] = Vh[base + sw1];
                }
                uint32_t fdA = gd_h[jp0 + r];
                uint32_t fdB = gd_h[jp0 + 4 + r];
                uint32_t selA = ck ? 0xEEAAu : 0xCC88u;
                uint32_t selB = ck ? 0xFFBBu : 0xDD99u;
                uint32_t Ah[2][4];
#pragma unroll
                for (int f = 0; f < 2; f++) {
#pragma unroll
                    for (int hh = 0; hh < 2; hh++) {
                        int t = 2*f + hh;
                        uint32_t amaskA = prmt_sr(us[t], vs[t], selA);
                        uint32_t amaskB = prmt_sr(us[t], vs[t], selB);
                        uint32_t eA = hadd2u(fs2h[t], fdA);
                        uint32_t eB = hadd2u(fs2h[t], fdB);
                        eA = hmax2u(eA, hmul2u(eA, C02H));
                        eB = hmax2u(eB, hmul2u(eB, C02H));
                        Ah[f][hh]     = ex2h2(eA) & amaskA;
                        Ah[f][2 + hh] = ex2h2(eB) & amaskB;
                    }
                }
#pragma unroll
                for (int nt = 0; nt < 2; nt++) {
#pragma unroll
                    for (int f = 0; f < 2; f++)
                        mma16h(acc[f][nt], Ah[f], Bf[nt][0], Bf[nt][1]);
                }
#pragma unroll
                for (int f = 0; f < 2; f++)
                    mma16h(accz[f], Ah[f], ONES16, ONES16);
            }
        }
    }

    if (jseg > 0) {
        float* dp = red + (((jseg - 1)*4 + rw)*32 + lane)*21;
        int c = 0;
#pragma unroll
        for (int f = 0; f < 2; f++)
#pragma unroll
            for (int nt = 0; nt < 2; nt++)
#pragma unroll
                for (int i = 0; i < 4; i++) dp[c++] = acc[f][nt][i];
        dp[16] = accz[0][0]; dp[17] = accz[0][2];
        dp[18] = accz[1][0]; dp[19] = accz[1][2];
    }
    __syncthreads();
    if (jseg == 0) {
        float z00 = accz[0][0], z02 = accz[0][2], z10 = accz[1][0], z12 = accz[1][2];
#pragma unroll
        for (int s = 0; s < 3; s++) {
            const float* sp = red + ((s*4 + rw)*32 + lane)*21;
            int c = 0;
#pragma unroll
            for (int f = 0; f < 2; f++)
#pragma unroll
                for (int nt = 0; nt < 2; nt++)
#pragma unroll
                    for (int i = 0; i < 4; i++) acc[f][nt][i] += sp[c++];
            z00 += sp[16]; z02 += sp[17]; z10 += sp[18]; z12 += sp[19];
        }
        float zz[2][2] = {{z00, z02}, {z10, z12}};
#pragma unroll
        for (int f = 0; f < 2; f++) {
#pragma unroll
            for (int hh = 0; hh < 2; hh++) {
                int row = row0 + rw*32 + q + 16*f + 8*hh;
                float inv = 1.f / zz[f][hh];
#pragma unroll
                for (int nt = 0; nt < 2; nt++) {
                    int col = nt*8 + 2*r;
                    if (nt == 0 || r < 2) {
                        float2 v;
                        v.x = eluf(acc[f][nt][2*hh]*inv);
                        v.y = eluf(acc[f][nt][2*hh + 1]*inv);
                        *(float2*)(out + (size_t)b*NN*NP + (size_t)row*NP + col) = v;
                    }
                }
            }
        }
    }
}

// ---------------- launch ----------------
extern "C" void kernel_launch(void* const* d_in, const int* in_sizes, int n_in,
                              void* d_out, int out_size) {
    const float* x         = (const float*)d_in[0];
    const int*   adj       = (const int*)  d_in[1];
    const float* W         = (const float*)d_in[2];
    const float* a_src     = (const float*)d_in[3];
    const float* a_dst     = (const float*)d_in[4];
    const float* W_out     = (const float*)d_in[5];
    const float* a_out_src = (const float*)d_in[6];
    const float* a_out_dst = (const float*)d_in[7];
    float* out = (float*)d_out;

    int smem1 = (32*512 + 512 + NHID*NP) * (int)sizeof(float);            // 69120 B
    int smem2 = (16*512 + 512 + NN + 3*4*32*21) * (int)sizeof(float);     // 71168 B
    cudaFuncSetAttribute(k_attn1_f, cudaFuncAttributeMaxDynamicSharedMemorySize, smem1);
    cudaFuncSetAttribute(k_attn2_m, cudaFuncAttributeMaxDynamicSharedMemorySize, smem2);

    k_wh<<<dim3(B*HEADS, NN*2/256), 256>>>(x, W, a_src, a_dst, adj);
    k_attn1_f<<<B*HEADS*2, 512, smem1>>>(W_out);
    k_attn2_m<<<B*8, 512, smem2>>>(out, a_out_src, a_out_dst);
}